// round 12
// baseline (speedup 1.0000x reference)
#include <cuda_runtime.h>
#include <cuda_fp16.h>
#include <cstdint>
#include <math.h>

#define B_ROWS 8192
#define D_DIM  4096
#define A_DIM  1024
#define H_DIM  128
#define C_DIM  16

// ---------------------------------------------------------------------------
// Scratch (module-scope device memory; no runtime allocation).
// ---------------------------------------------------------------------------
__device__ float  g_A[(size_t)B_ROWS * D_DIM];      // 128 MB: attention logits
__device__ float  g_H[B_ROWS * H_DIM];              // 4 MB  : relu(weighted@Wc1+bc1)
__device__ __half g_X[(size_t)B_ROWS * D_DIM];      // 64 MB : fp16(x), then fp16(weighted)
__device__ __half g_T[B_ROWS * A_DIM];              // 16 MB : fp16(tanh(x@W1+b1))
__device__ __half g_W1t[A_DIM * D_DIM];             // [N,K] = [1024,4096]
__device__ __half g_W2t[D_DIM * A_DIM];             // [4096,1024]
__device__ __half g_Wc1t[H_DIM * D_DIM];            // [128,4096]

// ---------------------------------------------------------------------------
// PTX helpers — baseline (non-'a') instructions only.
// ---------------------------------------------------------------------------
__device__ __forceinline__ uint32_t smem_to_u32(const void* p) {
    uint32_t a;
    asm("{ .reg .u64 t; cvta.to.shared.u64 t, %1; cvt.u32.u64 %0, t; }"
        : "=r"(a) : "l"(p));
    return a;
}

__device__ __forceinline__ void cp16(uint32_t saddr, const void* gaddr) {
    asm volatile("cp.async.cg.shared.global [%0], [%1], 16;"
                 :: "r"(saddr), "l"(gaddr));
}
#define CP_COMMIT()  asm volatile("cp.async.commit_group;" ::: "memory")
#define CP_WAIT(n)   asm volatile("cp.async.wait_group %0;" :: "n"(n) : "memory")

__device__ __forceinline__ void ldsm_x4(uint32_t* r, uint32_t addr) {
    asm volatile("ldmatrix.sync.aligned.m8n8.x4.shared.b16 {%0,%1,%2,%3}, [%4];"
                 : "=r"(r[0]), "=r"(r[1]), "=r"(r[2]), "=r"(r[3]) : "r"(addr));
}

// m16n8k16 fp16 MMA, fp32 accumulate.
__device__ __forceinline__ void mma16816(float* d, const uint32_t* a,
                                         const uint32_t* b) {
    asm volatile(
        "mma.sync.aligned.m16n8k16.row.col.f32.f16.f16.f32 "
        "{%0,%1,%2,%3}, {%4,%5,%6,%7}, {%8,%9}, {%0,%1,%2,%3};"
        : "+f"(d[0]), "+f"(d[1]), "+f"(d[2]), "+f"(d[3])
        : "r"(a[0]), "r"(a[1]), "r"(a[2]), "r"(a[3]), "r"(b[0]), "r"(b[1]));
}

__device__ __forceinline__ uint32_t pack_h2(float a, float b) {
    __half2 h = __floats2half2_rn(a, b);
    return *reinterpret_cast<uint32_t*>(&h);
}

__device__ __forceinline__ float warp_red_max(float v) {
    #pragma unroll
    for (int o = 16; o; o >>= 1)
        v = fmaxf(v, __shfl_xor_sync(0xffffffffu, v, o));
    return v;
}
__device__ __forceinline__ float warp_red_sum(float v) {
    #pragma unroll
    for (int o = 16; o; o >>= 1)
        v += __shfl_xor_sync(0xffffffffu, v, o);
    return v;
}
__device__ __forceinline__ int warp_red_sum_i(int v) {
    #pragma unroll
    for (int o = 16; o; o >>= 1)
        v += __shfl_xor_sync(0xffffffffu, v, o);
    return v;
}

// ---------------------------------------------------------------------------
// Weight prep: W[K,N] fp32 -> [N,K] fp16 (transpose + round).
// ---------------------------------------------------------------------------
__global__ void __launch_bounds__(256)
transpose_half_kernel(const float* __restrict__ W,
                      __half* __restrict__ T,
                      int K, int N)
{
    __shared__ float t[32][33];
    const int n0 = blockIdx.x * 32, k0 = blockIdx.y * 32;
    const int tx = threadIdx.x, ty = threadIdx.y;
    #pragma unroll
    for (int j = ty; j < 32; j += 8)
        t[j][tx] = W[(size_t)(k0 + j) * N + n0 + tx];
    __syncthreads();
    #pragma unroll
    for (int j = ty; j < 32; j += 8)
        T[(size_t)(n0 + j) * K + k0 + tx] = __float2half_rn(t[tx][j]);
}

// ---------------------------------------------------------------------------
// Activation convert: fp32 [M,K] -> fp16 [M,K].
// ---------------------------------------------------------------------------
__global__ void __launch_bounds__(256)
tohalf_kernel(const float4* __restrict__ in, uint2* __restrict__ out, int n4)
{
    int i = blockIdx.x * 256 + threadIdx.x;
    if (i < n4) {
        float4 v = in[i];
        uint2 o;
        o.x = pack_h2(v.x, v.y);
        o.y = pack_h2(v.z, v.w);
        out[i] = o;
    }
}

// ---------------------------------------------------------------------------
// Tensor-core GEMM via mma.sync (fp16, fp32 accum), single-term:
//   C = act( A @ B^T + bias ),  A fp16 [M,K] row-major, B fp16 [N,K] row-major.
// CTA tile BM x 128 (BM = MT*32), BK=32, 8 warps (2m x 4n), warp tile MT*16 x 32.
// cp.async 3-stage pipeline, 80B smem row pitch (R8/R11-validated skeleton).
// ACT: 0=identity, 1=tanh, 2=relu. OHALF: 1 -> write fp16, else fp32.
// ---------------------------------------------------------------------------
template<int MT, int ACT, int OHALF>
__global__ void __launch_bounds__(256, 1)
mma_gemm(const __half* __restrict__ A,
         const __half* __restrict__ B,
         const float* __restrict__ bias,
         float* __restrict__ Cf,
         __half* __restrict__ Ch,
         int M, int N, int K)
{
    constexpr int BM = MT * 32;
    constexpr int BK = 32;                     // fp16 elems per chunk
    constexpr int PITCH = 80;                  // bytes per smem row (32*2 + 16 pad)
    constexpr uint32_t OFF_B = (uint32_t)BM * PITCH;
    constexpr uint32_t BUFBYTES = OFF_B + 128 * PITCH;
    constexpr int AITER = (BM * 4) / 256;      // 16B transfers per thread (A)
    static_assert((BM * 4) % 256 == 0, "");

    extern __shared__ __align__(128) char smem[];
    const uint32_t sbase = smem_to_u32(smem);

    const int tid    = threadIdx.x;
    const int lane   = tid & 31;
    const int warp   = tid >> 5;
    const int warp_m = warp & 1;               // 2 warps along M
    const int warp_n = warp >> 1;              // 4 warps along N
    const int row0   = blockIdx.y * BM;
    const int col0   = blockIdx.x * 128;
    const int nch    = K / BK;

    float acc[MT][4][4];
    #pragma unroll
    for (int mi = 0; mi < MT; mi++)
        #pragma unroll
        for (int ni = 0; ni < 4; ni++)
            #pragma unroll
            for (int r = 0; r < 4; r++) acc[mi][ni][r] = 0.f;

    // ---- chunk loader (cp.async, 16B transfers); commit done by caller ----
    auto load_chunk = [&](int c, int buf) {
        const uint32_t sb = sbase + (uint32_t)buf * BUFBYTES;
        const int kc = c * BK;
        #pragma unroll
        for (int i = 0; i < AITER; i++) {
            int idx = tid + i * 256;
            int m = idx >> 2, seg = idx & 3;
            const __half* g = A + (size_t)(row0 + m) * K + kc + seg * 8;
            cp16(sb + m * PITCH + seg * 16, g);
        }
        #pragma unroll
        for (int i = 0; i < 2; i++) {
            int idx = tid + i * 256;
            int n = idx >> 2, seg = idx & 3;
            const __half* g = B + (size_t)(col0 + n) * K + kc + seg * 8;
            cp16(sb + OFF_B + n * PITCH + seg * 16, g);
        }
    };

    // Prologue: chunks 0 and 1 in flight (one commit group each).
    load_chunk(0, 0);
    CP_COMMIT();
    if (nch > 1) load_chunk(1, 1);
    CP_COMMIT();

    const int lm = lane & 15, lq = lane >> 4;         // A ldmatrix lane mapping
    const int bmat = lane >> 3, brow = lane & 7;      // B ldmatrix lane mapping

    for (int c = 0; c < nch; ++c) {
        // Keep two chunks ahead in flight; commit (possibly empty) every iter
        // so the group count stays in lockstep with c.
        if (c + 2 < nch) load_chunk(c + 2, (c + 2) % 3);
        CP_COMMIT();
        CP_WAIT(2);               // groups up to index c complete
        __syncthreads();

        const uint32_t sb = sbase + (uint32_t)(c % 3) * BUFBYTES;
        #pragma unroll
        for (int ks = 0; ks < 2; ks++) {              // two K=16 substeps
            uint32_t aR[MT][4];
            #pragma unroll
            for (int mi = 0; mi < MT; mi++) {
                uint32_t ra = sb +
                    (uint32_t)((warp_m * MT * 16 + mi * 16 + lm) * PITCH +
                               ks * 32 + lq * 16);
                ldsm_x4(aR[mi], ra);
            }
            uint32_t bR[4][2];
            #pragma unroll
            for (int tp = 0; tp < 2; tp++) {
                int t  = tp * 2 + (bmat >> 1);
                int kh = bmat & 1;
                uint32_t rb = sb + OFF_B +
                    (uint32_t)((warp_n * 32 + t * 8 + brow) * PITCH +
                               ks * 32 + kh * 16);
                uint32_t q[4];
                ldsm_x4(q, rb);
                bR[tp*2][0] = q[0]; bR[tp*2][1] = q[1];
                bR[tp*2+1][0] = q[2]; bR[tp*2+1][1] = q[3];
            }
            #pragma unroll
            for (int mi = 0; mi < MT; mi++)
                #pragma unroll
                for (int ni = 0; ni < 4; ni++)
                    mma16816(acc[mi][ni], aR[mi], bR[ni]);
        }
        __syncthreads();          // ldsm reads done before buffer reuse
    }

    // ---- epilogue: bias + activation, fp32 or fp16 output ----
    #pragma unroll
    for (int mi = 0; mi < MT; mi++) {
        #pragma unroll
        for (int ni = 0; ni < 4; ni++) {
            int rbase = row0 + warp_m * MT * 16 + mi * 16 + (lane >> 2);
            int cb    = col0 + warp_n * 32 + ni * 8 + (lane & 3) * 2;
            float b0 = bias[cb], b1 = bias[cb + 1];
            #pragma unroll
            for (int h = 0; h < 2; h++) {
                float v0 = acc[mi][ni][2*h + 0] + b0;
                float v1 = acc[mi][ni][2*h + 1] + b1;
                if (ACT == 1) { v0 = tanhf(v0); v1 = tanhf(v1); }
                if (ACT == 2) { v0 = fmaxf(v0, 0.f); v1 = fmaxf(v1, 0.f); }
                size_t o = (size_t)(rbase + h * 8) * N + cb;
                if (OHALF) {
                    *reinterpret_cast<uint32_t*>(&Ch[o]) = pack_h2(v0, v1);
                } else {
                    float2 ov; ov.x = v0; ov.y = v1;
                    *reinterpret_cast<float2*>(&Cf[o]) = ov;
                }
            }
        }
    }
}

// ---------------------------------------------------------------------------
// Fused sparsemax + gating, one block per row. Warp-shuffle reductions.
// Writes weighted = x * sparsemax(Z) directly as fp16 (GEMM3 input).
// ---------------------------------------------------------------------------
__global__ void __launch_bounds__(256)
sparsemax_gate_kernel(const float* __restrict__ Z, const float* __restrict__ X,
                      __half* __restrict__ Wh)
{
    __shared__ float z[D_DIM];
    __shared__ float swarp[8];
    __shared__ int   cwarp[8];

    const int tid  = threadIdx.x;
    const int lane = tid & 31;
    const int wid  = tid >> 5;
    const size_t roff = (size_t)blockIdx.x * D_DIM;

    for (int i = tid; i < D_DIM / 4; i += 256)
        reinterpret_cast<float4*>(z)[i] =
            reinterpret_cast<const float4*>(Z + roff)[i];
    __syncthreads();

    float m = -3.402823466e38f;
    for (int i = tid; i < D_DIM; i += 256) m = fmaxf(m, z[i]);
    m = warp_red_max(m);
    if (lane == 0) swarp[wid] = m;
    __syncthreads();
    float tau;
    {
        float m8 = -3.402823466e38f;
        #pragma unroll
        for (int w = 0; w < 8; w++) m8 = fmaxf(m8, swarp[w]);
        tau = m8 - 1.0f;          // f(tau0) >= 0 guaranteed
    }

    for (int it = 0; it < 32; ++it) {
        float s = 0.f; int c = 0;
        for (int i = tid; i < D_DIM; i += 256) {
            float d = z[i] - tau;
            if (d > 0.f) { s += d; c++; }
        }
        s = warp_red_sum(s);
        c = warp_red_sum_i(c);
        __syncthreads();
        if (lane == 0) { swarp[wid] = s; cwarp[wid] = c; }
        __syncthreads();
        float S = 0.f; int C = 0;
        #pragma unroll
        for (int w = 0; w < 8; w++) { S += swarp[w]; C += cwarp[w]; }
        if (C == 0) break;
        float delta = (S - 1.0f) / (float)C;
        tau += delta;
        if (fabsf(delta) <= 1e-7f) break;
    }

    const float* xr = X + roff;
    for (int i = tid; i < D_DIM / 4; i += 256) {
        float4 zv = reinterpret_cast<const float4*>(z)[i];
        float4 xv = reinterpret_cast<const float4*>(xr)[i];
        float w0 = xv.x * fmaxf(zv.x - tau, 0.f);
        float w1 = xv.y * fmaxf(zv.y - tau, 0.f);
        float w2 = xv.z * fmaxf(zv.z - tau, 0.f);
        float w3 = xv.w * fmaxf(zv.w - tau, 0.f);
        uint2 o;
        o.x = pack_h2(w0, w1);
        o.y = pack_h2(w2, w3);
        reinterpret_cast<uint2*>(Wh + roff)[i] = o;
    }
}

// ---------------------------------------------------------------------------
// Final tiny GEMM: out[B,16] = Hh[B,128] @ Wc2[128,16] + bc2.
// ---------------------------------------------------------------------------
__global__ void __launch_bounds__(256)
final_gemm_kernel(const float* __restrict__ Hh, const float* __restrict__ Wc2,
                  const float* __restrict__ bc2, float* __restrict__ out)
{
    __shared__ float sH[16][H_DIM];
    __shared__ float sW[H_DIM][C_DIM];

    const int tid  = threadIdx.x;
    const int row0 = blockIdx.x * 16;

    for (int i = tid; i < 16 * H_DIM / 4; i += 256) {
        int r = i / (H_DIM / 4);
        int c = (i % (H_DIM / 4)) * 4;
        *reinterpret_cast<float4*>(&sH[r][c]) =
            *reinterpret_cast<const float4*>(&Hh[(size_t)(row0 + r) * H_DIM + c]);
    }
    for (int i = tid; i < H_DIM * C_DIM / 4; i += 256) {
        int k = i / (C_DIM / 4);
        int c = (i % (C_DIM / 4)) * 4;
        *reinterpret_cast<float4*>(&sW[k][c]) =
            *reinterpret_cast<const float4*>(&Wc2[k * C_DIM + c]);
    }
    __syncthreads();

    const int r = tid / C_DIM;
    const int c = tid % C_DIM;
    float s = bc2[c];
    #pragma unroll
    for (int k = 0; k < H_DIM; k++) s += sH[r][k] * sW[k][c];
    out[(size_t)(row0 + r) * C_DIM + c] = s;
}

// ---------------------------------------------------------------------------
// Launch sequence (graph-capturable: kernel launches only).
// ---------------------------------------------------------------------------
extern "C" void kernel_launch(void* const* d_in, const int* in_sizes, int n_in,
                              void* d_out, int out_size)
{
    const float* x   = (const float*)d_in[0];
    const float* W1  = (const float*)d_in[1];
    const float* b1  = (const float*)d_in[2];
    const float* W2  = (const float*)d_in[3];
    const float* b2  = (const float*)d_in[4];
    const float* Wc1 = (const float*)d_in[5];
    const float* bc1 = (const float*)d_in[6];
    const float* Wc2 = (const float*)d_in[7];
    const float* bc2 = (const float*)d_in[8];
    float* out = (float*)d_out;
    (void)in_sizes; (void)n_in; (void)out_size;

    float *pA, *pH;
    __half *pX, *pT, *pW1t, *pW2t, *pWc1t;
    cudaGetSymbolAddress((void**)&pA,    g_A);
    cudaGetSymbolAddress((void**)&pH,    g_H);
    cudaGetSymbolAddress((void**)&pX,    g_X);
    cudaGetSymbolAddress((void**)&pT,    g_T);
    cudaGetSymbolAddress((void**)&pW1t,  g_W1t);
    cudaGetSymbolAddress((void**)&pW2t,  g_W2t);
    cudaGetSymbolAddress((void**)&pWc1t, g_Wc1t);

    // Dynamic smem: 3 stages * (BM + 128) * 80 bytes
    const int SMEM_MT4 = 3 * (128 + 128) * 80;   // 61440
    const int SMEM_MT2 = 3 * (64 + 128) * 80;    // 46080
    cudaFuncSetAttribute(mma_gemm<4,1,1>, cudaFuncAttributeMaxDynamicSharedMemorySize, SMEM_MT4);
    cudaFuncSetAttribute(mma_gemm<4,0,0>, cudaFuncAttributeMaxDynamicSharedMemorySize, SMEM_MT4);
    cudaFuncSetAttribute(mma_gemm<2,2,0>, cudaFuncAttributeMaxDynamicSharedMemorySize, SMEM_MT2);

    // 0) Weight prep: transpose + fp16 round.
    transpose_half_kernel<<<dim3(A_DIM / 32, D_DIM / 32), dim3(32, 8)>>>(
        W1, pW1t, D_DIM, A_DIM);
    transpose_half_kernel<<<dim3(D_DIM / 32, A_DIM / 32), dim3(32, 8)>>>(
        W2, pW2t, A_DIM, D_DIM);
    transpose_half_kernel<<<dim3(H_DIM / 32, D_DIM / 32), dim3(32, 8)>>>(
        Wc1, pWc1t, D_DIM, H_DIM);

    // 0b) Convert x -> fp16.
    {
        int n4 = B_ROWS * D_DIM / 4;
        tohalf_kernel<<<n4 / 256, 256>>>((const float4*)x, (uint2*)pX, n4);
    }

    // 1) T = tanh(x @ W1 + b1), written as fp16.  [8192,1024], K=4096
    mma_gemm<4,1,1><<<dim3(A_DIM / 128, B_ROWS / 128), 256, SMEM_MT4>>>(
        pX, pW1t, b1, nullptr, pT, B_ROWS, A_DIM, D_DIM);

    // 2) a = T @ W2 + b2 (fp32)          [8192,4096], K=1024
    mma_gemm<4,0,0><<<dim3(D_DIM / 128, B_ROWS / 128), 256, SMEM_MT4>>>(
        pT, pW2t, b2, pA, nullptr, B_ROWS, D_DIM, A_DIM);

    // 3) weighted = x * sparsemax(a), written as fp16 into g_X.
    sparsemax_gate_kernel<<<B_ROWS, 256>>>(pA, x, pX);

    // 4) h = relu(weighted @ Wc1 + bc1)  [8192,128], K=4096
    mma_gemm<2,2,0><<<dim3(H_DIM / 128, B_ROWS / 64), 256, SMEM_MT2>>>(
        pX, pWc1t, bc1, pH, nullptr, B_ROWS, H_DIM, D_DIM);

    // 5) out = h @ Wc2 + bc2             [8192,16], K=128
    final_gemm_kernel<<<B_ROWS / 16, 256>>>(pH, Wc2, bc2, out);
}

// round 14
// speedup vs baseline: 2.0794x; 2.0794x over previous
#include <cuda_runtime.h>
#include <cuda_fp16.h>
#include <cstdint>
#include <math.h>

#define B_ROWS 8192
#define D_DIM  4096
#define A_DIM  1024
#define H_DIM  128
#define C_DIM  16

// ---------------------------------------------------------------------------
// Scratch (module-scope device memory; no runtime allocation).
// ---------------------------------------------------------------------------
__device__ float  g_A[(size_t)B_ROWS * D_DIM];      // 128 MB: attention logits
__device__ float  g_H[B_ROWS * H_DIM];              // 4 MB  : relu(weighted@Wc1+bc1)
__device__ __half g_X[(size_t)B_ROWS * D_DIM];      // 64 MB : fp16(x), then fp16(weighted)
__device__ __half g_T[B_ROWS * A_DIM];              // 16 MB : fp16(tanh(x@W1+b1))
__device__ __half g_W1t[A_DIM * D_DIM];             // [N,K] = [1024,4096]
__device__ __half g_W2t[D_DIM * A_DIM];             // [4096,1024]
__device__ __half g_Wc1t[H_DIM * D_DIM];            // [128,4096]

// ---------------------------------------------------------------------------
// PTX helpers — baseline (non-'a') instructions only.
// ---------------------------------------------------------------------------
__device__ __forceinline__ uint32_t smem_to_u32(const void* p) {
    uint32_t a;
    asm("{ .reg .u64 t; cvta.to.shared.u64 t, %1; cvt.u32.u64 %0, t; }"
        : "=r"(a) : "l"(p));
    return a;
}

__device__ __forceinline__ void cp16(uint32_t saddr, const void* gaddr) {
    asm volatile("cp.async.cg.shared.global [%0], [%1], 16;"
                 :: "r"(saddr), "l"(gaddr));
}
#define CP_COMMIT()  asm volatile("cp.async.commit_group;" ::: "memory")
#define CP_WAIT(n)   asm volatile("cp.async.wait_group %0;" :: "n"(n) : "memory")

__device__ __forceinline__ void ldsm_x4(uint32_t* r, uint32_t addr) {
    asm volatile("ldmatrix.sync.aligned.m8n8.x4.shared.b16 {%0,%1,%2,%3}, [%4];"
                 : "=r"(r[0]), "=r"(r[1]), "=r"(r[2]), "=r"(r[3]) : "r"(addr));
}

// m16n8k16 fp16 MMA, fp32 accumulate.
__device__ __forceinline__ void mma16816(float* d, const uint32_t* a,
                                         const uint32_t* b) {
    asm volatile(
        "mma.sync.aligned.m16n8k16.row.col.f32.f16.f16.f32 "
        "{%0,%1,%2,%3}, {%4,%5,%6,%7}, {%8,%9}, {%0,%1,%2,%3};"
        : "+f"(d[0]), "+f"(d[1]), "+f"(d[2]), "+f"(d[3])
        : "r"(a[0]), "r"(a[1]), "r"(a[2]), "r"(a[3]), "r"(b[0]), "r"(b[1]));
}

__device__ __forceinline__ uint32_t pack_h2(float a, float b) {
    __half2 h = __floats2half2_rn(a, b);
    return *reinterpret_cast<uint32_t*>(&h);
}

__device__ __forceinline__ float warp_red_max(float v) {
    #pragma unroll
    for (int o = 16; o; o >>= 1)
        v = fmaxf(v, __shfl_xor_sync(0xffffffffu, v, o));
    return v;
}
__device__ __forceinline__ float warp_red_sum(float v) {
    #pragma unroll
    for (int o = 16; o; o >>= 1)
        v += __shfl_xor_sync(0xffffffffu, v, o);
    return v;
}
__device__ __forceinline__ int warp_red_sum_i(int v) {
    #pragma unroll
    for (int o = 16; o; o >>= 1)
        v += __shfl_xor_sync(0xffffffffu, v, o);
    return v;
}

// ---------------------------------------------------------------------------
// Weight prep: W[K,N] fp32 -> [N,K] fp16 (transpose + round).
// ---------------------------------------------------------------------------
__global__ void __launch_bounds__(256)
transpose_half_kernel(const float* __restrict__ W,
                      __half* __restrict__ T,
                      int K, int N)
{
    __shared__ float t[32][33];
    const int n0 = blockIdx.x * 32, k0 = blockIdx.y * 32;
    const int tx = threadIdx.x, ty = threadIdx.y;
    #pragma unroll
    for (int j = ty; j < 32; j += 8)
        t[j][tx] = W[(size_t)(k0 + j) * N + n0 + tx];
    __syncthreads();
    #pragma unroll
    for (int j = ty; j < 32; j += 8)
        T[(size_t)(n0 + j) * K + k0 + tx] = __float2half_rn(t[tx][j]);
}

// ---------------------------------------------------------------------------
// Activation convert: fp32 [M,K] -> fp16 [M,K].
// ---------------------------------------------------------------------------
__global__ void __launch_bounds__(256)
tohalf_kernel(const float4* __restrict__ in, uint2* __restrict__ out, int n4)
{
    int i = blockIdx.x * 256 + threadIdx.x;
    if (i < n4) {
        float4 v = in[i];
        uint2 o;
        o.x = pack_h2(v.x, v.y);
        o.y = pack_h2(v.z, v.w);
        out[i] = o;
    }
}

// ---------------------------------------------------------------------------
// Tensor-core GEMM via mma.sync (fp16, fp32 accum), single-term:
//   C = act( A @ B^T + bias ),  A fp16 [M,K] row-major, B fp16 [N,K] row-major.
// CTA tile BM x 128 (BM = MT*32), BK=64, 8 warps (2m x 4n), warp tile MT*16 x 32.
// cp.async 3-stage pipeline (halved chunk count vs BK=32), 144B smem row pitch
// (64 halfs + 16B pad; 144 mod 128 = 16 -> conflict-free ldmatrix).
// Two CTAs co-reside per SM (3*36.9KB*2 = 221KB smem) to overlap chunk latency.
// ACT: 0=identity, 1=tanh, 2=relu. OHALF: 1 -> write fp16, else fp32.
// ---------------------------------------------------------------------------
template<int MT, int ACT, int OHALF>
__global__ void __launch_bounds__(256)
mma_gemm(const __half* __restrict__ A,
         const __half* __restrict__ B,
         const float* __restrict__ bias,
         float* __restrict__ Cf,
         __half* __restrict__ Ch,
         int M, int N, int K)
{
    constexpr int BM = MT * 32;
    constexpr int BK = 64;                     // fp16 elems per chunk
    constexpr int PITCH = 144;                 // bytes per smem row (64*2 + 16 pad)
    constexpr uint32_t OFF_B = (uint32_t)BM * PITCH;
    constexpr uint32_t BUFBYTES = OFF_B + 128 * PITCH;
    constexpr int AITER = (BM * 8) / 256;      // 16B transfers per thread (A)
    static_assert((BM * 8) % 256 == 0, "");

    extern __shared__ __align__(128) char smem[];
    const uint32_t sbase = smem_to_u32(smem);

    const int tid    = threadIdx.x;
    const int lane   = tid & 31;
    const int warp   = tid >> 5;
    const int warp_m = warp & 1;               // 2 warps along M
    const int warp_n = warp >> 1;              // 4 warps along N
    const int row0   = blockIdx.y * BM;
    const int col0   = blockIdx.x * 128;
    const int nch    = K / BK;

    float acc[MT][4][4];
    #pragma unroll
    for (int mi = 0; mi < MT; mi++)
        #pragma unroll
        for (int ni = 0; ni < 4; ni++)
            #pragma unroll
            for (int r = 0; r < 4; r++) acc[mi][ni][r] = 0.f;

    // ---- chunk loader (cp.async, 16B transfers); commit done by caller ----
    auto load_chunk = [&](int c, int buf) {
        const uint32_t sb = sbase + (uint32_t)buf * BUFBYTES;
        const int kc = c * BK;
        #pragma unroll
        for (int i = 0; i < AITER; i++) {
            int idx = tid + i * 256;
            int m = idx >> 3, seg = idx & 7;
            const __half* g = A + (size_t)(row0 + m) * K + kc + seg * 8;
            cp16(sb + m * PITCH + seg * 16, g);
        }
        #pragma unroll
        for (int i = 0; i < 4; i++) {
            int idx = tid + i * 256;
            int n = idx >> 3, seg = idx & 7;
            const __half* g = B + (size_t)(col0 + n) * K + kc + seg * 8;
            cp16(sb + OFF_B + n * PITCH + seg * 16, g);
        }
    };

    // Prologue: chunks 0 and 1 in flight (one commit group each).
    load_chunk(0, 0);
    CP_COMMIT();
    if (nch > 1) load_chunk(1, 1);
    CP_COMMIT();

    const int lm = lane & 15, lq = lane >> 4;         // A ldmatrix lane mapping
    const int bmat = lane >> 3, brow = lane & 7;      // B ldmatrix lane mapping

    for (int c = 0; c < nch; ++c) {
        // Keep two chunks ahead in flight; commit (possibly empty) every iter
        // so the group count stays in lockstep with c.
        if (c + 2 < nch) load_chunk(c + 2, (c + 2) % 3);
        CP_COMMIT();
        CP_WAIT(2);               // groups up to index c complete
        __syncthreads();

        const uint32_t sb = sbase + (uint32_t)(c % 3) * BUFBYTES;
        #pragma unroll
        for (int ks = 0; ks < 4; ks++) {              // four K=16 substeps
            uint32_t aR[MT][4];
            #pragma unroll
            for (int mi = 0; mi < MT; mi++) {
                uint32_t ra = sb +
                    (uint32_t)((warp_m * MT * 16 + mi * 16 + lm) * PITCH +
                               ks * 32 + lq * 16);
                ldsm_x4(aR[mi], ra);
            }
            uint32_t bR[4][2];
            #pragma unroll
            for (int tp = 0; tp < 2; tp++) {
                int t  = tp * 2 + (bmat >> 1);
                int kh = bmat & 1;
                uint32_t rb = sb + OFF_B +
                    (uint32_t)((warp_n * 32 + t * 8 + brow) * PITCH +
                               ks * 32 + kh * 16);
                uint32_t q[4];
                ldsm_x4(q, rb);
                bR[tp*2][0] = q[0]; bR[tp*2][1] = q[1];
                bR[tp*2+1][0] = q[2]; bR[tp*2+1][1] = q[3];
            }
            #pragma unroll
            for (int mi = 0; mi < MT; mi++)
                #pragma unroll
                for (int ni = 0; ni < 4; ni++)
                    mma16816(acc[mi][ni], aR[mi], bR[ni]);
        }
        __syncthreads();          // ldsm reads done before buffer reuse
    }

    // ---- epilogue: bias + activation, fp32 or fp16 output ----
    #pragma unroll
    for (int mi = 0; mi < MT; mi++) {
        #pragma unroll
        for (int ni = 0; ni < 4; ni++) {
            int rbase = row0 + warp_m * MT * 16 + mi * 16 + (lane >> 2);
            int cb    = col0 + warp_n * 32 + ni * 8 + (lane & 3) * 2;
            float b0 = bias[cb], b1 = bias[cb + 1];
            #pragma unroll
            for (int h = 0; h < 2; h++) {
                float v0 = acc[mi][ni][2*h + 0] + b0;
                float v1 = acc[mi][ni][2*h + 1] + b1;
                if (ACT == 1) { v0 = tanhf(v0); v1 = tanhf(v1); }
                if (ACT == 2) { v0 = fmaxf(v0, 0.f); v1 = fmaxf(v1, 0.f); }
                size_t o = (size_t)(rbase + h * 8) * N + cb;
                if (OHALF) {
                    *reinterpret_cast<uint32_t*>(&Ch[o]) = pack_h2(v0, v1);
                } else {
                    float2 ov; ov.x = v0; ov.y = v1;
                    *reinterpret_cast<float2*>(&Cf[o]) = ov;
                }
            }
        }
    }
}

// ---------------------------------------------------------------------------
// Fused sparsemax + gating, one block per row. Warp-shuffle reductions.
// Writes weighted = x * sparsemax(Z) directly as fp16 (GEMM3 input).
// ---------------------------------------------------------------------------
__global__ void __launch_bounds__(256)
sparsemax_gate_kernel(const float* __restrict__ Z, const float* __restrict__ X,
                      __half* __restrict__ Wh)
{
    __shared__ float z[D_DIM];
    __shared__ float swarp[8];
    __shared__ int   cwarp[8];

    const int tid  = threadIdx.x;
    const int lane = tid & 31;
    const int wid  = tid >> 5;
    const size_t roff = (size_t)blockIdx.x * D_DIM;

    for (int i = tid; i < D_DIM / 4; i += 256)
        reinterpret_cast<float4*>(z)[i] =
            reinterpret_cast<const float4*>(Z + roff)[i];
    __syncthreads();

    float m = -3.402823466e38f;
    for (int i = tid; i < D_DIM; i += 256) m = fmaxf(m, z[i]);
    m = warp_red_max(m);
    if (lane == 0) swarp[wid] = m;
    __syncthreads();
    float tau;
    {
        float m8 = -3.402823466e38f;
        #pragma unroll
        for (int w = 0; w < 8; w++) m8 = fmaxf(m8, swarp[w]);
        tau = m8 - 1.0f;          // f(tau0) >= 0 guaranteed
    }

    for (int it = 0; it < 20; ++it) {
        float s = 0.f; int c = 0;
        for (int i = tid; i < D_DIM; i += 256) {
            float d = z[i] - tau;
            if (d > 0.f) { s += d; c++; }
        }
        s = warp_red_sum(s);
        c = warp_red_sum_i(c);
        __syncthreads();
        if (lane == 0) { swarp[wid] = s; cwarp[wid] = c; }
        __syncthreads();
        float S = 0.f; int C = 0;
        #pragma unroll
        for (int w = 0; w < 8; w++) { S += swarp[w]; C += cwarp[w]; }
        if (C == 0) break;
        float delta = (S - 1.0f) / (float)C;
        tau += delta;
        if (fabsf(delta) <= 1e-7f) break;
    }

    const float* xr = X + roff;
    for (int i = tid; i < D_DIM / 4; i += 256) {
        float4 zv = reinterpret_cast<const float4*>(z)[i];
        float4 xv = reinterpret_cast<const float4*>(xr)[i];
        float w0 = xv.x * fmaxf(zv.x - tau, 0.f);
        float w1 = xv.y * fmaxf(zv.y - tau, 0.f);
        float w2 = xv.z * fmaxf(zv.z - tau, 0.f);
        float w3 = xv.w * fmaxf(zv.w - tau, 0.f);
        uint2 o;
        o.x = pack_h2(w0, w1);
        o.y = pack_h2(w2, w3);
        reinterpret_cast<uint2*>(Wh + roff)[i] = o;
    }
}

// ---------------------------------------------------------------------------
// Final tiny GEMM: out[B,16] = Hh[B,128] @ Wc2[128,16] + bc2.
// ---------------------------------------------------------------------------
__global__ void __launch_bounds__(256)
final_gemm_kernel(const float* __restrict__ Hh, const float* __restrict__ Wc2,
                  const float* __restrict__ bc2, float* __restrict__ out)
{
    __shared__ float sH[16][H_DIM];
    __shared__ float sW[H_DIM][C_DIM];

    const int tid  = threadIdx.x;
    const int row0 = blockIdx.x * 16;

    for (int i = tid; i < 16 * H_DIM / 4; i += 256) {
        int r = i / (H_DIM / 4);
        int c = (i % (H_DIM / 4)) * 4;
        *reinterpret_cast<float4*>(&sH[r][c]) =
            *reinterpret_cast<const float4*>(&Hh[(size_t)(row0 + r) * H_DIM + c]);
    }
    for (int i = tid; i < H_DIM * C_DIM / 4; i += 256) {
        int k = i / (C_DIM / 4);
        int c = (i % (C_DIM / 4)) * 4;
        *reinterpret_cast<float4*>(&sW[k][c]) =
            *reinterpret_cast<const float4*>(&Wc2[k * C_DIM + c]);
    }
    __syncthreads();

    const int r = tid / C_DIM;
    const int c = tid % C_DIM;
    float s = bc2[c];
    #pragma unroll
    for (int k = 0; k < H_DIM; k++) s += sH[r][k] * sW[k][c];
    out[(size_t)(row0 + r) * C_DIM + c] = s;
}

// ---------------------------------------------------------------------------
// Launch sequence (graph-capturable: kernel launches only).
// ---------------------------------------------------------------------------
extern "C" void kernel_launch(void* const* d_in, const int* in_sizes, int n_in,
                              void* d_out, int out_size)
{
    const float* x   = (const float*)d_in[0];
    const float* W1  = (const float*)d_in[1];
    const float* b1  = (const float*)d_in[2];
    const float* W2  = (const float*)d_in[3];
    const float* b2  = (const float*)d_in[4];
    const float* Wc1 = (const float*)d_in[5];
    const float* bc1 = (const float*)d_in[6];
    const float* Wc2 = (const float*)d_in[7];
    const float* bc2 = (const float*)d_in[8];
    float* out = (float*)d_out;
    (void)in_sizes; (void)n_in; (void)out_size;

    float *pA, *pH;
    __half *pX, *pT, *pW1t, *pW2t, *pWc1t;
    cudaGetSymbolAddress((void**)&pA,    g_A);
    cudaGetSymbolAddress((void**)&pH,    g_H);
    cudaGetSymbolAddress((void**)&pX,    g_X);
    cudaGetSymbolAddress((void**)&pT,    g_T);
    cudaGetSymbolAddress((void**)&pW1t,  g_W1t);
    cudaGetSymbolAddress((void**)&pW2t,  g_W2t);
    cudaGetSymbolAddress((void**)&pWc1t, g_Wc1t);

    // Dynamic smem: 3 stages * (BM + 128) * 144 bytes
    const int SMEM_MT4 = 3 * (128 + 128) * 144;   // 110592 (2 CTAs/SM: 221184)
    const int SMEM_MT2 = 3 * (64 + 128) * 144;    // 82944
    cudaFuncSetAttribute(mma_gemm<4,1,1>, cudaFuncAttributeMaxDynamicSharedMemorySize, SMEM_MT4);
    cudaFuncSetAttribute(mma_gemm<4,0,0>, cudaFuncAttributeMaxDynamicSharedMemorySize, SMEM_MT4);
    cudaFuncSetAttribute(mma_gemm<2,2,0>, cudaFuncAttributeMaxDynamicSharedMemorySize, SMEM_MT2);

    // 0) Weight prep: transpose + fp16 round.
    transpose_half_kernel<<<dim3(A_DIM / 32, D_DIM / 32), dim3(32, 8)>>>(
        W1, pW1t, D_DIM, A_DIM);
    transpose_half_kernel<<<dim3(D_DIM / 32, A_DIM / 32), dim3(32, 8)>>>(
        W2, pW2t, A_DIM, D_DIM);
    transpose_half_kernel<<<dim3(H_DIM / 32, D_DIM / 32), dim3(32, 8)>>>(
        Wc1, pWc1t, D_DIM, H_DIM);

    // 0b) Convert x -> fp16.
    {
        int n4 = B_ROWS * D_DIM / 4;
        tohalf_kernel<<<n4 / 256, 256>>>((const float4*)x, (uint2*)pX, n4);
    }

    // 1) T = tanh(x @ W1 + b1), written as fp16.  [8192,1024], K=4096
    mma_gemm<4,1,1><<<dim3(A_DIM / 128, B_ROWS / 128), 256, SMEM_MT4>>>(
        pX, pW1t, b1, nullptr, pT, B_ROWS, A_DIM, D_DIM);

    // 2) a = T @ W2 + b2 (fp32)          [8192,4096], K=1024
    mma_gemm<4,0,0><<<dim3(D_DIM / 128, B_ROWS / 128), 256, SMEM_MT4>>>(
        pT, pW2t, b2, pA, nullptr, B_ROWS, D_DIM, A_DIM);

    // 3) weighted = x * sparsemax(a), written as fp16 into g_X.
    sparsemax_gate_kernel<<<B_ROWS, 256>>>(pA, x, pX);

    // 4) h = relu(weighted @ Wc1 + bc1)  [8192,128], K=4096
    mma_gemm<2,2,0><<<dim3(H_DIM / 128, B_ROWS / 64), 256, SMEM_MT2>>>(
        pX, pWc1t, bc1, pH, nullptr, B_ROWS, H_DIM, D_DIM);

    // 5) out = h @ Wc2 + bc2             [8192,16], K=128
    final_gemm_kernel<<<B_ROWS / 16, 256>>>(pH, Wc2, bc2, out);
}

// round 16
// speedup vs baseline: 2.1331x; 1.0258x over previous
#include <cuda_runtime.h>
#include <cuda_fp16.h>
#include <cstdint>
#include <math.h>

#define B_ROWS 8192
#define D_DIM  4096
#define A_DIM  1024
#define H_DIM  128
#define C_DIM  16

// ---------------------------------------------------------------------------
// Scratch (module-scope device memory; no runtime allocation).
// ---------------------------------------------------------------------------
__device__ float  g_A[(size_t)B_ROWS * D_DIM];      // 128 MB: attention logits
__device__ float  g_H[B_ROWS * H_DIM];              // 4 MB  : relu(weighted@Wc1+bc1)
__device__ __half g_X[(size_t)B_ROWS * D_DIM];      // 64 MB : fp16(x), then fp16(weighted)
__device__ __half g_T[B_ROWS * A_DIM];              // 16 MB : fp16(tanh(x@W1+b1))
__device__ __half g_W1t[A_DIM * D_DIM];             // [N,K] = [1024,4096]
__device__ __half g_W2t[D_DIM * A_DIM];             // [4096,1024]
__device__ __half g_Wc1t[H_DIM * D_DIM];            // [128,4096]

// ---------------------------------------------------------------------------
// PTX helpers — baseline (non-'a') instructions only.
// ---------------------------------------------------------------------------
__device__ __forceinline__ uint32_t smem_to_u32(const void* p) {
    uint32_t a;
    asm("{ .reg .u64 t; cvta.to.shared.u64 t, %1; cvt.u32.u64 %0, t; }"
        : "=r"(a) : "l"(p));
    return a;
}

__device__ __forceinline__ void cp16(uint32_t saddr, const void* gaddr) {
    asm volatile("cp.async.cg.shared.global [%0], [%1], 16;"
                 :: "r"(saddr), "l"(gaddr));
}
#define CP_COMMIT()  asm volatile("cp.async.commit_group;" ::: "memory")
#define CP_WAIT(n)   asm volatile("cp.async.wait_group %0;" :: "n"(n) : "memory")

__device__ __forceinline__ void ldsm_x4(uint32_t* r, uint32_t addr) {
    asm volatile("ldmatrix.sync.aligned.m8n8.x4.shared.b16 {%0,%1,%2,%3}, [%4];"
                 : "=r"(r[0]), "=r"(r[1]), "=r"(r[2]), "=r"(r[3]) : "r"(addr));
}

// m16n8k16 fp16 MMA, fp32 accumulate.
__device__ __forceinline__ void mma16816(float* d, const uint32_t* a,
                                         const uint32_t* b) {
    asm volatile(
        "mma.sync.aligned.m16n8k16.row.col.f32.f16.f16.f32 "
        "{%0,%1,%2,%3}, {%4,%5,%6,%7}, {%8,%9}, {%0,%1,%2,%3};"
        : "+f"(d[0]), "+f"(d[1]), "+f"(d[2]), "+f"(d[3])
        : "r"(a[0]), "r"(a[1]), "r"(a[2]), "r"(a[3]), "r"(b[0]), "r"(b[1]));
}

__device__ __forceinline__ uint32_t pack_h2(float a, float b) {
    __half2 h = __floats2half2_rn(a, b);
    return *reinterpret_cast<uint32_t*>(&h);
}

__device__ __forceinline__ float warp_red_max(float v) {
    #pragma unroll
    for (int o = 16; o; o >>= 1)
        v = fmaxf(v, __shfl_xor_sync(0xffffffffu, v, o));
    return v;
}
__device__ __forceinline__ float warp_red_sum(float v) {
    #pragma unroll
    for (int o = 16; o; o >>= 1)
        v += __shfl_xor_sync(0xffffffffu, v, o);
    return v;
}
__device__ __forceinline__ int warp_red_sum_i(int v) {
    #pragma unroll
    for (int o = 16; o; o >>= 1)
        v += __shfl_xor_sync(0xffffffffu, v, o);
    return v;
}

// ---------------------------------------------------------------------------
// Weight prep: W[K,N] fp32 -> [N,K] fp16 (transpose + round).
// ---------------------------------------------------------------------------
__global__ void __launch_bounds__(256)
transpose_half_kernel(const float* __restrict__ W,
                      __half* __restrict__ T,
                      int K, int N)
{
    __shared__ float t[32][33];
    const int n0 = blockIdx.x * 32, k0 = blockIdx.y * 32;
    const int tx = threadIdx.x, ty = threadIdx.y;
    #pragma unroll
    for (int j = ty; j < 32; j += 8)
        t[j][tx] = W[(size_t)(k0 + j) * N + n0 + tx];
    __syncthreads();
    #pragma unroll
    for (int j = ty; j < 32; j += 8)
        T[(size_t)(n0 + j) * K + k0 + tx] = __float2half_rn(t[tx][j]);
}

// ---------------------------------------------------------------------------
// Activation convert: fp32 [M,K] -> fp16 [M,K].
// ---------------------------------------------------------------------------
__global__ void __launch_bounds__(256)
tohalf_kernel(const float4* __restrict__ in, uint2* __restrict__ out, int n4)
{
    int i = blockIdx.x * 256 + threadIdx.x;
    if (i < n4) {
        float4 v = in[i];
        uint2 o;
        o.x = pack_h2(v.x, v.y);
        o.y = pack_h2(v.z, v.w);
        out[i] = o;
    }
}

// ---------------------------------------------------------------------------
// Tensor-core GEMM via mma.sync (fp16, fp32 accum), single-term:
//   C = act( A @ B^T + bias ),  A fp16 [M,K] row-major, B fp16 [N,K] row-major.
// CTA tile BM x 128 (BM = MT*32), BK=64, 8 warps (2m x 4n), warp tile MT*16 x 32.
// cp.async 3-stage pipeline, 144B smem row pitch, 2 CTAs/SM.
// ONE __syncthreads per chunk: the top-of-iteration barrier both publishes
// chunk c's data and guards reuse of buffer (c+2)%3 == (c-1)%3 (whose reads
// all completed in iteration c-1). Uniform CP_WAIT(1): chunk c's commit group
// is always second-newest at the wait (every iteration commits exactly one
// group, possibly empty, keeping the count in lockstep).
// ACT: 0=identity, 1=tanh, 2=relu. OHALF: 1 -> write fp16, else fp32.
// ---------------------------------------------------------------------------
template<int MT, int ACT, int OHALF>
__global__ void __launch_bounds__(256)
mma_gemm(const __half* __restrict__ A,
         const __half* __restrict__ B,
         const float* __restrict__ bias,
         float* __restrict__ Cf,
         __half* __restrict__ Ch,
         int M, int N, int K)
{
    constexpr int BM = MT * 32;
    constexpr int BK = 64;                     // fp16 elems per chunk
    constexpr int PITCH = 144;                 // bytes per smem row (64*2 + 16 pad)
    constexpr uint32_t OFF_B = (uint32_t)BM * PITCH;
    constexpr uint32_t BUFBYTES = OFF_B + 128 * PITCH;
    constexpr int AITER = (BM * 8) / 256;      // 16B transfers per thread (A)
    static_assert((BM * 8) % 256 == 0, "");

    extern __shared__ __align__(128) char smem[];
    const uint32_t sbase = smem_to_u32(smem);

    const int tid    = threadIdx.x;
    const int lane   = tid & 31;
    const int warp   = tid >> 5;
    const int warp_m = warp & 1;               // 2 warps along M
    const int warp_n = warp >> 1;              // 4 warps along N
    const int row0   = blockIdx.y * BM;
    const int col0   = blockIdx.x * 128;
    const int nch    = K / BK;

    float acc[MT][4][4];
    #pragma unroll
    for (int mi = 0; mi < MT; mi++)
        #pragma unroll
        for (int ni = 0; ni < 4; ni++)
            #pragma unroll
            for (int r = 0; r < 4; r++) acc[mi][ni][r] = 0.f;

    // ---- chunk loader (cp.async, 16B transfers); commit done by caller ----
    auto load_chunk = [&](int c, int buf) {
        const uint32_t sb = sbase + (uint32_t)buf * BUFBYTES;
        const int kc = c * BK;
        #pragma unroll
        for (int i = 0; i < AITER; i++) {
            int idx = tid + i * 256;
            int m = idx >> 3, seg = idx & 7;
            const __half* g = A + (size_t)(row0 + m) * K + kc + seg * 8;
            cp16(sb + m * PITCH + seg * 16, g);
        }
        #pragma unroll
        for (int i = 0; i < 4; i++) {
            int idx = tid + i * 256;
            int n = idx >> 3, seg = idx & 7;
            const __half* g = B + (size_t)(col0 + n) * K + kc + seg * 8;
            cp16(sb + OFF_B + n * PITCH + seg * 16, g);
        }
    };

    // Prologue: chunks 0 and 1 in flight (one commit group each).
    load_chunk(0, 0);
    CP_COMMIT();
    if (nch > 1) load_chunk(1, 1);
    CP_COMMIT();

    const int lm = lane & 15, lq = lane >> 4;         // A ldmatrix lane mapping
    const int bmat = lane >> 3, brow = lane & 7;      // B ldmatrix lane mapping

    for (int c = 0; c < nch; ++c) {
        // Chunk c's group is second-newest (iteration c-1 committed chunk c+1,
        // possibly empty) -> WAIT(1) guarantees chunk c landed.
        CP_WAIT(1);
        __syncthreads();          // publish chunk c; also: all reads of buffer
                                  // (c-1)%3 (== (c+2)%3) finished last iter.
        if (c + 2 < nch) load_chunk(c + 2, (c + 2) % 3);
        CP_COMMIT();              // commit every iter (possibly empty) to keep
                                  // group count in lockstep with c.

        const uint32_t sb = sbase + (uint32_t)(c % 3) * BUFBYTES;
        #pragma unroll
        for (int ks = 0; ks < 4; ks++) {              // four K=16 substeps
            uint32_t aR[MT][4];
            #pragma unroll
            for (int mi = 0; mi < MT; mi++) {
                uint32_t ra = sb +
                    (uint32_t)((warp_m * MT * 16 + mi * 16 + lm) * PITCH +
                               ks * 32 + lq * 16);
                ldsm_x4(aR[mi], ra);
            }
            uint32_t bR[4][2];
            #pragma unroll
            for (int tp = 0; tp < 2; tp++) {
                int t  = tp * 2 + (bmat >> 1);
                int kh = bmat & 1;
                uint32_t rb = sb + OFF_B +
                    (uint32_t)((warp_n * 32 + t * 8 + brow) * PITCH +
                               ks * 32 + kh * 16);
                uint32_t q[4];
                ldsm_x4(q, rb);
                bR[tp*2][0] = q[0]; bR[tp*2][1] = q[1];
                bR[tp*2+1][0] = q[2]; bR[tp*2+1][1] = q[3];
            }
            #pragma unroll
            for (int mi = 0; mi < MT; mi++)
                #pragma unroll
                for (int ni = 0; ni < 4; ni++)
                    mma16816(acc[mi][ni], aR[mi], bR[ni]);
        }
    }

    // ---- epilogue: bias + activation, fp32 or fp16 output ----
    #pragma unroll
    for (int mi = 0; mi < MT; mi++) {
        #pragma unroll
        for (int ni = 0; ni < 4; ni++) {
            int rbase = row0 + warp_m * MT * 16 + mi * 16 + (lane >> 2);
            int cb    = col0 + warp_n * 32 + ni * 8 + (lane & 3) * 2;
            float b0 = bias[cb], b1 = bias[cb + 1];
            #pragma unroll
            for (int h = 0; h < 2; h++) {
                float v0 = acc[mi][ni][2*h + 0] + b0;
                float v1 = acc[mi][ni][2*h + 1] + b1;
                if (ACT == 1) { v0 = tanhf(v0); v1 = tanhf(v1); }
                if (ACT == 2) { v0 = fmaxf(v0, 0.f); v1 = fmaxf(v1, 0.f); }
                size_t o = (size_t)(rbase + h * 8) * N + cb;
                if (OHALF) {
                    *reinterpret_cast<uint32_t*>(&Ch[o]) = pack_h2(v0, v1);
                } else {
                    float2 ov; ov.x = v0; ov.y = v1;
                    *reinterpret_cast<float2*>(&Cf[o]) = ov;
                }
            }
        }
    }
}

// ---------------------------------------------------------------------------
// Fused sparsemax + gating, one block per row. Warp-shuffle reductions.
// Writes weighted = x * sparsemax(Z) directly as fp16 (GEMM3 input).
// ---------------------------------------------------------------------------
__global__ void __launch_bounds__(256)
sparsemax_gate_kernel(const float* __restrict__ Z, const float* __restrict__ X,
                      __half* __restrict__ Wh)
{
    __shared__ float z[D_DIM];
    __shared__ float swarp[8];
    __shared__ int   cwarp[8];

    const int tid  = threadIdx.x;
    const int lane = tid & 31;
    const int wid  = tid >> 5;
    const size_t roff = (size_t)blockIdx.x * D_DIM;

    for (int i = tid; i < D_DIM / 4; i += 256)
        reinterpret_cast<float4*>(z)[i] =
            reinterpret_cast<const float4*>(Z + roff)[i];
    __syncthreads();

    float m = -3.402823466e38f;
    for (int i = tid; i < D_DIM; i += 256) m = fmaxf(m, z[i]);
    m = warp_red_max(m);
    if (lane == 0) swarp[wid] = m;
    __syncthreads();
    float tau;
    {
        float m8 = -3.402823466e38f;
        #pragma unroll
        for (int w = 0; w < 8; w++) m8 = fmaxf(m8, swarp[w]);
        tau = m8 - 1.0f;          // f(tau0) >= 0 guaranteed
    }

    for (int it = 0; it < 20; ++it) {
        float s = 0.f; int c = 0;
        for (int i = tid; i < D_DIM; i += 256) {
            float d = z[i] - tau;
            if (d > 0.f) { s += d; c++; }
        }
        s = warp_red_sum(s);
        c = warp_red_sum_i(c);
        __syncthreads();
        if (lane == 0) { swarp[wid] = s; cwarp[wid] = c; }
        __syncthreads();
        float S = 0.f; int C = 0;
        #pragma unroll
        for (int w = 0; w < 8; w++) { S += swarp[w]; C += cwarp[w]; }
        if (C == 0) break;
        float delta = (S - 1.0f) / (float)C;
        tau += delta;
        if (fabsf(delta) <= 1e-7f) break;
    }

    const float* xr = X + roff;
    for (int i = tid; i < D_DIM / 4; i += 256) {
        float4 zv = reinterpret_cast<const float4*>(z)[i];
        float4 xv = reinterpret_cast<const float4*>(xr)[i];
        float w0 = xv.x * fmaxf(zv.x - tau, 0.f);
        float w1 = xv.y * fmaxf(zv.y - tau, 0.f);
        float w2 = xv.z * fmaxf(zv.z - tau, 0.f);
        float w3 = xv.w * fmaxf(zv.w - tau, 0.f);
        uint2 o;
        o.x = pack_h2(w0, w1);
        o.y = pack_h2(w2, w3);
        reinterpret_cast<uint2*>(Wh + roff)[i] = o;
    }
}

// ---------------------------------------------------------------------------
// Final tiny GEMM: out[B,16] = Hh[B,128] @ Wc2[128,16] + bc2.
// ---------------------------------------------------------------------------
__global__ void __launch_bounds__(256)
final_gemm_kernel(const float* __restrict__ Hh, const float* __restrict__ Wc2,
                  const float* __restrict__ bc2, float* __restrict__ out)
{
    __shared__ float sH[16][H_DIM];
    __shared__ float sW[H_DIM][C_DIM];

    const int tid  = threadIdx.x;
    const int row0 = blockIdx.x * 16;

    for (int i = tid; i < 16 * H_DIM / 4; i += 256) {
        int r = i / (H_DIM / 4);
        int c = (i % (H_DIM / 4)) * 4;
        *reinterpret_cast<float4*>(&sH[r][c]) =
            *reinterpret_cast<const float4*>(&Hh[(size_t)(row0 + r) * H_DIM + c]);
    }
    for (int i = tid; i < H_DIM * C_DIM / 4; i += 256) {
        int k = i / (C_DIM / 4);
        int c = (i % (C_DIM / 4)) * 4;
        *reinterpret_cast<float4*>(&sW[k][c]) =
            *reinterpret_cast<const float4*>(&Wc2[k * C_DIM + c]);
    }
    __syncthreads();

    const int r = tid / C_DIM;
    const int c = tid % C_DIM;
    float s = bc2[c];
    #pragma unroll
    for (int k = 0; k < H_DIM; k++) s += sH[r][k] * sW[k][c];
    out[(size_t)(row0 + r) * C_DIM + c] = s;
}

// ---------------------------------------------------------------------------
// Launch sequence (graph-capturable: kernel launches only).
// ---------------------------------------------------------------------------
extern "C" void kernel_launch(void* const* d_in, const int* in_sizes, int n_in,
                              void* d_out, int out_size)
{
    const float* x   = (const float*)d_in[0];
    const float* W1  = (const float*)d_in[1];
    const float* b1  = (const float*)d_in[2];
    const float* W2  = (const float*)d_in[3];
    const float* b2  = (const float*)d_in[4];
    const float* Wc1 = (const float*)d_in[5];
    const float* bc1 = (const float*)d_in[6];
    const float* Wc2 = (const float*)d_in[7];
    const float* bc2 = (const float*)d_in[8];
    float* out = (float*)d_out;
    (void)in_sizes; (void)n_in; (void)out_size;

    float *pA, *pH;
    __half *pX, *pT, *pW1t, *pW2t, *pWc1t;
    cudaGetSymbolAddress((void**)&pA,    g_A);
    cudaGetSymbolAddress((void**)&pH,    g_H);
    cudaGetSymbolAddress((void**)&pX,    g_X);
    cudaGetSymbolAddress((void**)&pT,    g_T);
    cudaGetSymbolAddress((void**)&pW1t,  g_W1t);
    cudaGetSymbolAddress((void**)&pW2t,  g_W2t);
    cudaGetSymbolAddress((void**)&pWc1t, g_Wc1t);

    // Dynamic smem: 3 stages * (BM + 128) * 144 bytes
    const int SMEM_MT4 = 3 * (128 + 128) * 144;   // 110592 (2 CTAs/SM: 221184)
    const int SMEM_MT2 = 3 * (64 + 128) * 144;    // 82944
    cudaFuncSetAttribute(mma_gemm<4,1,1>, cudaFuncAttributeMaxDynamicSharedMemorySize, SMEM_MT4);
    cudaFuncSetAttribute(mma_gemm<4,0,0>, cudaFuncAttributeMaxDynamicSharedMemorySize, SMEM_MT4);
    cudaFuncSetAttribute(mma_gemm<2,2,0>, cudaFuncAttributeMaxDynamicSharedMemorySize, SMEM_MT2);

    // 0) Weight prep: transpose + fp16 round.
    transpose_half_kernel<<<dim3(A_DIM / 32, D_DIM / 32), dim3(32, 8)>>>(
        W1, pW1t, D_DIM, A_DIM);
    transpose_half_kernel<<<dim3(D_DIM / 32, A_DIM / 32), dim3(32, 8)>>>(
        W2, pW2t, A_DIM, D_DIM);
    transpose_half_kernel<<<dim3(H_DIM / 32, D_DIM / 32), dim3(32, 8)>>>(
        Wc1, pWc1t, D_DIM, H_DIM);

    // 0b) Convert x -> fp16.
    {
        int n4 = B_ROWS * D_DIM / 4;
        tohalf_kernel<<<n4 / 256, 256>>>((const float4*)x, (uint2*)pX, n4);
    }

    // 1) T = tanh(x @ W1 + b1), written as fp16.  [8192,1024], K=4096
    mma_gemm<4,1,1><<<dim3(A_DIM / 128, B_ROWS / 128), 256, SMEM_MT4>>>(
        pX, pW1t, b1, nullptr, pT, B_ROWS, A_DIM, D_DIM);

    // 2) a = T @ W2 + b2 (fp32)          [8192,4096], K=1024
    mma_gemm<4,0,0><<<dim3(D_DIM / 128, B_ROWS / 128), 256, SMEM_MT4>>>(
        pT, pW2t, b2, pA, nullptr, B_ROWS, D_DIM, A_DIM);

    // 3) weighted = x * sparsemax(a), written as fp16 into g_X.
    sparsemax_gate_kernel<<<B_ROWS, 256>>>(pA, x, pX);

    // 4) h = relu(weighted @ Wc1 + bc1)  [8192,128], K=4096
    mma_gemm<2,2,0><<<dim3(H_DIM / 128, B_ROWS / 64), 256, SMEM_MT2>>>(
        pX, pWc1t, bc1, pH, nullptr, B_ROWS, H_DIM, D_DIM);

    // 5) out = h @ Wc2 + bc2             [8192,16], K=128
    final_gemm_kernel<<<B_ROWS / 16, 256>>>(pH, Wc2, bc2, out);
}